// round 7
// baseline (speedup 1.0000x reference)
#include <cuda_runtime.h>
#include <cfloat>
#include <cstdint>

// Problem constants (fixed shapes from reference)
#define PB   2
#define PH   4
#define PLQ  512
#define PLKV 512
#define PD   64
#define PBH  (PB * PH)     // 8
#define TQ   8             // q-rows per block in main kernel

// Scratch for projected q/k (allocation-free rule: __device__ globals)
__device__ __align__(16) float g_qp[PBH * PLQ * PD];   // qp + b_concat folded in
__device__ __align__(16) float g_kp[PBH * PLKV * PD];

__device__ __forceinline__ float tanh_fast(float x) {
    float r;
    asm("tanh.approx.f32 %0, %1;" : "=f"(r) : "f"(x));
    return r;
}

// ---------------------------------------------------------------------------
// Projection, tiled: 64 rows per block, W-half staged in smem (coalesced).
//   qp[r,e] = sum_d Q[r,d]*W[e,d] + bias[e]   (blocks 0..63)
//   kp[r,e] = sum_d K[r,d]*W[e,D+d]           (blocks 64..127)
// W_concat is (D, 2D) row-major. smem row stride 68 floats: 16B-aligned and
// conflict-free per LDS.128 phase (bank = 4e+c covers all 32 banks per phase).
// Thread (e = tid&63, rg = tid>>6) computes rows rg*16..rg*16+15 at column e.
// ---------------------------------------------------------------------------
__global__ __launch_bounds__(256) void proj_kernel(
    const float* __restrict__ Q, const float* __restrict__ K,
    const float* __restrict__ W, const float* __restrict__ bias)
{
    __shared__ __align__(16) float sW[PD][68];
    __shared__ __align__(16) float sIn[64][68];

    const int tid = threadIdx.x;
    const int r0  = blockIdx.x * 64;               // global row among 2*BH*LQ
    const bool isQ = (r0 < PBH * PLQ);
    const int rr0  = isQ ? r0 : (r0 - PBH * PLQ);
    const float* in = (isQ ? Q : K) + (size_t)rr0 * PD;
    const int woff = isQ ? 0 : PD;

    // Stage 64 input rows (coalesced float4)
    for (int i = tid; i < 64 * (PD / 4); i += 256) {
        int r = i >> 4, d4 = i & 15;
        float4 v = ((const float4*)(in + (size_t)r * PD))[d4];
        *(float4*)&sIn[r][d4 * 4] = v;
    }
    // Stage W half (e-major rows)
    for (int i = tid; i < PD * (PD / 4); i += 256) {
        int e = i >> 4, d4 = i & 15;
        float4 v = *(const float4*)(W + (size_t)e * (2 * PD) + woff + d4 * 4);
        *(float4*)&sW[e][d4 * 4] = v;
    }
    __syncthreads();

    const int e  = tid & 63;
    const int rg = tid >> 6;       // 4 groups x 16 rows
    const float b = isQ ? bias[e] : 0.0f;

    float acc[16];
#pragma unroll
    for (int r = 0; r < 16; r++) acc[r] = b;

#pragma unroll
    for (int d4 = 0; d4 < PD / 4; d4++) {
        float4 wv = *(const float4*)&sW[e][d4 * 4];
#pragma unroll
        for (int r = 0; r < 16; r++) {
            float4 iv = *(const float4*)&sIn[rg * 16 + r][d4 * 4]; // broadcast
            acc[r] += wv.x * iv.x + wv.y * iv.y + wv.z * iv.z + wv.w * iv.w;
        }
    }

    float* dst = (isQ ? g_qp : g_kp) + (size_t)rr0 * PD;
#pragma unroll
    for (int r = 0; r < 16; r++)
        dst[(size_t)(rg * 16 + r) * PD + e] = acc[r];   // coalesced STG.32
}

// ---------------------------------------------------------------------------
// Main kernel: one block = (bh, 8 consecutive q rows), all 512 k.
//   Phase 1: logits[q][k] = sum_e w[e]*tanh(qp[q,e] + kp[k,e])
//     kp streamed in 2 halves of 32 (ka[8] float4) + persistent acc[TQ];
//     target <=84 regs so __launch_bounds__(256,3) gives 3 CTAs/SM (24 warps)
//     to saturate the MUFU pipe (previous version: 168 regs, occ 12%).
//   Phase 2: per-warp masked softmax over each q row, write weights.
// Grid: BH * (LQ/TQ) = 512 blocks, 256 threads.
// ---------------------------------------------------------------------------
__global__ __launch_bounds__(256, 3) void attn_kernel(
    const int* __restrict__ mask,
    const float* __restrict__ w_logit,
    float* __restrict__ out)
{
    __shared__ __align__(16) float qp_s[TQ][PD];   // 2 KB
    __shared__ __align__(16) float ws[PD];         // 256 B
    __shared__ float logits_s[TQ][PLKV];           // 16 KB

    const int bh  = blockIdx.x / (PLQ / TQ);
    const int qt  = blockIdx.x % (PLQ / TQ);
    const int q0  = qt * TQ;
    const int tid = threadIdx.x;

    // Load qp tile (TQ*D = 512 floats) and w_logit into shared
    const float* qpbase = g_qp + ((size_t)bh * PLQ + q0) * PD;
    for (int i = tid; i < TQ * PD; i += 256)
        ((float*)qp_s)[i] = qpbase[i];
    if (tid < PD) ws[tid] = w_logit[tid];
    __syncthreads();

    const float*  kpbase = g_kp + (size_t)bh * PLKV * PD;
    const float4* ws4    = (const float4*)ws;

    // ---- Phase 1: logits ----
    for (int c = 0; c < PLKV; c += 256) {
        const int k = c + tid;
        const float4* kp4 = (const float4*)(kpbase + (size_t)k * PD);

        float acc[TQ];
#pragma unroll
        for (int q = 0; q < TQ; q++) acc[q] = 0.0f;

#pragma unroll
        for (int half = 0; half < 2; half++) {
            float4 ka[8];                       // 32 e-values of kp
#pragma unroll
            for (int i = 0; i < 8; i++) ka[i] = kp4[half * 8 + i];  // batched LDG

#pragma unroll
            for (int q = 0; q < TQ; q++) {
                const float4* qp4 = (const float4*)qp_s[q];
                float a0 = 0.0f, a1 = 0.0f;
#pragma unroll
                for (int e4 = 0; e4 < 8; e4++) {
                    float4 qv = qp4[half * 8 + e4];   // broadcast LDS.128
                    float4 wv = ws4[half * 8 + e4];   // broadcast LDS.128
                    a0 += wv.x * tanh_fast(qv.x + ka[e4].x);
                    a1 += wv.y * tanh_fast(qv.y + ka[e4].y);
                    a0 += wv.z * tanh_fast(qv.z + ka[e4].z);
                    a1 += wv.w * tanh_fast(qv.w + ka[e4].w);
                }
                acc[q] += a0 + a1;
            }
        }
#pragma unroll
        for (int q = 0; q < TQ; q++)
            logits_s[q][k] = acc[q];
    }
    __syncthreads();

    // ---- Phase 2: masked softmax, one warp per q row ----
    const int w    = tid >> 5;
    const int lane = tid & 31;
    const int qg   = q0 + w;
    const int b    = bh / PH;
    const int* mrow = mask + ((size_t)b * PLQ + qg) * PLKV;

    float m_val = -FLT_MAX, m_raw = -FLT_MAX;
    int anyv = 0;
    for (int j = lane; j < PLKV; j += 32) {
        float l = logits_s[w][j];
        int   v = mrow[j] != 0;
        anyv |= v;
        m_raw = fmaxf(m_raw, l);
        if (v) m_val = fmaxf(m_val, l);
    }
#pragma unroll
    for (int o = 16; o; o >>= 1) {
        m_val = fmaxf(m_val, __shfl_xor_sync(0xffffffffu, m_val, o));
        m_raw = fmaxf(m_raw, __shfl_xor_sync(0xffffffffu, m_raw, o));
    }
    const bool any = __ballot_sync(0xffffffffu, anyv) != 0;
    const float M = any ? m_val : m_raw;

    float s = 0.0f;
    for (int j = lane; j < PLKV; j += 32) {
        float l = logits_s[w][j];
        bool  v = (!any) || (mrow[j] != 0);
        float p = v ? __expf(l - M) : 0.0f;
        logits_s[w][j] = p;
        s += p;
    }
#pragma unroll
    for (int o = 16; o; o >>= 1)
        s += __shfl_xor_sync(0xffffffffu, s, o);
    const float inv = 1.0f / s;

    float* orow = out + ((size_t)bh * PLQ + qg) * PLKV;
    for (int j = lane; j < PLKV; j += 32)
        orow[j] = logits_s[w][j] * inv;
}

// ---------------------------------------------------------------------------
// Inputs (metadata order): queries, keys, values(unused), mask(int32),
// W_concat, b_concat, w_logit, b_logit(unused: softmax shift-invariant)
// ---------------------------------------------------------------------------
extern "C" void kernel_launch(void* const* d_in, const int* in_sizes, int n_in,
                              void* d_out, int out_size)
{
    const float* Q    = (const float*)d_in[0];
    const float* K    = (const float*)d_in[1];
    const int*   mask = (const int*)d_in[3];
    const float* W    = (const float*)d_in[4];
    const float* bc   = (const float*)d_in[5];
    const float* wl   = (const float*)d_in[6];
    float*       out  = (float*)d_out;

    proj_kernel<<<(2 * PBH * PLQ) / 64, 256>>>(Q, K, W, bc);
    attn_kernel<<<PBH * (PLQ / TQ), 256>>>(mask, wl, out);
}

// round 9
// speedup vs baseline: 1.3485x; 1.3485x over previous
#include <cuda_runtime.h>
#include <cfloat>
#include <cstdint>

// Problem constants (fixed shapes from reference)
#define PB   2
#define PH   4
#define PLQ  512
#define PLKV 512
#define PD   64
#define PBH  (PB * PH)     // 8
#define TQ   8             // q-rows per block in main kernel

// Scratch for projected q/k (allocation-free rule: __device__ globals)
__device__ __align__(16) float g_qp[PBH * PLQ * PD];   // qp + b_concat folded in
__device__ __align__(16) float g_kp[PBH * PLKV * PD];

__device__ __forceinline__ float tanh_fast(float x) {
    float r;
    asm("tanh.approx.f32 %0, %1;" : "=f"(r) : "f"(x));
    return r;
}

// ---------------------------------------------------------------------------
// Projection, tiled: 64 rows per block, W-half staged in smem (coalesced).
// (Measured good in R7: proj+overhead ~7.5us. Unchanged.)
// ---------------------------------------------------------------------------
__global__ __launch_bounds__(256) void proj_kernel(
    const float* __restrict__ Q, const float* __restrict__ K,
    const float* __restrict__ W, const float* __restrict__ bias)
{
    __shared__ __align__(16) float sW[PD][68];
    __shared__ __align__(16) float sIn[64][68];

    const int tid = threadIdx.x;
    const int r0  = blockIdx.x * 64;               // global row among 2*BH*LQ
    const bool isQ = (r0 < PBH * PLQ);
    const int rr0  = isQ ? r0 : (r0 - PBH * PLQ);
    const float* in = (isQ ? Q : K) + (size_t)rr0 * PD;
    const int woff = isQ ? 0 : PD;

    // Stage 64 input rows (coalesced float4)
    for (int i = tid; i < 64 * (PD / 4); i += 256) {
        int r = i >> 4, d4 = i & 15;
        float4 v = ((const float4*)(in + (size_t)r * PD))[d4];
        *(float4*)&sIn[r][d4 * 4] = v;
    }
    // Stage W half (e-major rows)
    for (int i = tid; i < PD * (PD / 4); i += 256) {
        int e = i >> 4, d4 = i & 15;
        float4 v = *(const float4*)(W + (size_t)e * (2 * PD) + woff + d4 * 4);
        *(float4*)&sW[e][d4 * 4] = v;
    }
    __syncthreads();

    const int e  = tid & 63;
    const int rg = tid >> 6;       // 4 groups x 16 rows
    const float b = isQ ? bias[e] : 0.0f;

    float acc[16];
#pragma unroll
    for (int r = 0; r < 16; r++) acc[r] = b;

#pragma unroll
    for (int d4 = 0; d4 < PD / 4; d4++) {
        float4 wv = *(const float4*)&sW[e][d4 * 4];
#pragma unroll
        for (int r = 0; r < 16; r++) {
            float4 iv = *(const float4*)&sIn[rg * 16 + r][d4 * 4]; // broadcast
            acc[r] += wv.x * iv.x + wv.y * iv.y + wv.z * iv.z + wv.w * iv.w;
        }
    }

    float* dst = (isQ ? g_qp : g_kp) + (size_t)rr0 * PD;
#pragma unroll
    for (int r = 0; r < 16; r++)
        dst[(size_t)(rg * 16 + r) * PD + e] = acc[r];   // coalesced STG.32
}

// ---------------------------------------------------------------------------
// Main kernel: one block = (bh, 8 consecutive q rows), all 512 k.
//   Phase 1: logits[q][k] = sum_e w[e]*tanh(qp[q,e] + kp[k,e])
//     kp streamed in QUARTERS (ka[4] = 16 regs) + persistent acc[TQ].
//     R7 lesson: the (256,3)/84-reg budget SPILLED (DRAM 30%, issue 8%).
//     Natural demand ~115-125 regs -> cap at 128 via (256,2): spill-free,
//     2 CTAs/SM = 16 warps (4/SMSP) vs R5's 8 warps (2/SMSP, issue 21%).
//   Phase 2: per-warp masked softmax over each q row, write weights.
// Grid: BH * (LQ/TQ) = 512 blocks, 256 threads.
// ---------------------------------------------------------------------------
__global__ __launch_bounds__(256, 2) void attn_kernel(
    const int* __restrict__ mask,
    const float* __restrict__ w_logit,
    float* __restrict__ out)
{
    __shared__ __align__(16) float qp_s[TQ][PD];   // 2 KB
    __shared__ __align__(16) float ws[PD];         // 256 B
    __shared__ float logits_s[TQ][PLKV];           // 16 KB

    const int bh  = blockIdx.x / (PLQ / TQ);
    const int qt  = blockIdx.x % (PLQ / TQ);
    const int q0  = qt * TQ;
    const int tid = threadIdx.x;

    // Load qp tile (TQ*D = 512 floats) and w_logit into shared
    const float* qpbase = g_qp + ((size_t)bh * PLQ + q0) * PD;
    for (int i = tid; i < TQ * PD; i += 256)
        ((float*)qp_s)[i] = qpbase[i];
    if (tid < PD) ws[tid] = w_logit[tid];
    __syncthreads();

    const float*  kpbase = g_kp + (size_t)bh * PLKV * PD;
    const float4* ws4    = (const float4*)ws;

    // ---- Phase 1: logits ----
    for (int c = 0; c < PLKV; c += 256) {
        const int k = c + tid;
        const float4* kp4 = (const float4*)(kpbase + (size_t)k * PD);

        float acc[TQ];
#pragma unroll
        for (int q = 0; q < TQ; q++) acc[q] = 0.0f;

#pragma unroll
        for (int quarter = 0; quarter < 4; quarter++) {
            float4 ka[4];                       // 16 e-values of kp
#pragma unroll
            for (int i = 0; i < 4; i++) ka[i] = kp4[quarter * 4 + i]; // batched LDG

#pragma unroll
            for (int q = 0; q < TQ; q++) {
                const float4* qp4 = (const float4*)qp_s[q];
                float a0 = 0.0f, a1 = 0.0f;
#pragma unroll
                for (int e4 = 0; e4 < 4; e4++) {
                    float4 qv = qp4[quarter * 4 + e4];   // broadcast LDS.128
                    float4 wv = ws4[quarter * 4 + e4];   // broadcast LDS.128
                    a0 += wv.x * tanh_fast(qv.x + ka[e4].x);
                    a1 += wv.y * tanh_fast(qv.y + ka[e4].y);
                    a0 += wv.z * tanh_fast(qv.z + ka[e4].z);
                    a1 += wv.w * tanh_fast(qv.w + ka[e4].w);
                }
                acc[q] += a0 + a1;
            }
        }
#pragma unroll
        for (int q = 0; q < TQ; q++)
            logits_s[q][k] = acc[q];
    }
    __syncthreads();

    // ---- Phase 2: masked softmax, one warp per q row ----
    const int w    = tid >> 5;
    const int lane = tid & 31;
    const int qg   = q0 + w;
    const int b    = bh / PH;
    const int* mrow = mask + ((size_t)b * PLQ + qg) * PLKV;

    float m_val = -FLT_MAX, m_raw = -FLT_MAX;
    int anyv = 0;
    for (int j = lane; j < PLKV; j += 32) {
        float l = logits_s[w][j];
        int   v = mrow[j] != 0;
        anyv |= v;
        m_raw = fmaxf(m_raw, l);
        if (v) m_val = fmaxf(m_val, l);
    }
#pragma unroll
    for (int o = 16; o; o >>= 1) {
        m_val = fmaxf(m_val, __shfl_xor_sync(0xffffffffu, m_val, o));
        m_raw = fmaxf(m_raw, __shfl_xor_sync(0xffffffffu, m_raw, o));
    }
    const bool any = __ballot_sync(0xffffffffu, anyv) != 0;
    const float M = any ? m_val : m_raw;

    float s = 0.0f;
    for (int j = lane; j < PLKV; j += 32) {
        float l = logits_s[w][j];
        bool  v = (!any) || (mrow[j] != 0);
        float p = v ? __expf(l - M) : 0.0f;
        logits_s[w][j] = p;
        s += p;
    }
#pragma unroll
    for (int o = 16; o; o >>= 1)
        s += __shfl_xor_sync(0xffffffffu, s, o);
    const float inv = 1.0f / s;

    float* orow = out + ((size_t)bh * PLQ + qg) * PLKV;
    for (int j = lane; j < PLKV; j += 32)
        orow[j] = logits_s[w][j] * inv;
}

// ---------------------------------------------------------------------------
// Inputs (metadata order): queries, keys, values(unused), mask(int32),
// W_concat, b_concat, w_logit, b_logit(unused: softmax shift-invariant)
// ---------------------------------------------------------------------------
extern "C" void kernel_launch(void* const* d_in, const int* in_sizes, int n_in,
                              void* d_out, int out_size)
{
    const float* Q    = (const float*)d_in[0];
    const float* K    = (const float*)d_in[1];
    const int*   mask = (const int*)d_in[3];
    const float* W    = (const float*)d_in[4];
    const float* bc   = (const float*)d_in[5];
    const float* wl   = (const float*)d_in[6];
    float*       out  = (float*)d_out;

    proj_kernel<<<(2 * PBH * PLQ) / 64, 256>>>(Q, K, W, bc);
    attn_kernel<<<PBH * (PLQ / TQ), 256>>>(mask, wl, out);
}

// round 12
// speedup vs baseline: 3.5139x; 2.6058x over previous
#include <cuda_runtime.h>
#include <cfloat>
#include <cstdint>

// Problem constants (fixed shapes from reference)
#define PB   2
#define PH   4
#define PLQ  512
#define PLKV 512
#define PD   64
#define PBH  (PB * PH)     // 8
#define TQ   4             // q-rows per block (R9 lesson: TQ=8 needs >=150 regs)

// Scratch for projected q/k (allocation-free rule: __device__ globals)
__device__ __align__(16) float g_qp[PBH * PLQ * PD];   // qp + b_concat folded in
__device__ __align__(16) float g_kp[PBH * PLKV * PD];

__device__ __forceinline__ float tanh_fast(float x) {
    float r;
    asm("tanh.approx.f32 %0, %1;" : "=f"(r) : "f"(x));
    return r;
}

// ---------------------------------------------------------------------------
// Projection, tiled: 64 rows per block, W-half staged in smem (coalesced).
// (Measured good: proj+overhead ~7.5us. Unchanged.)
// ---------------------------------------------------------------------------
__global__ __launch_bounds__(256) void proj_kernel(
    const float* __restrict__ Q, const float* __restrict__ K,
    const float* __restrict__ W, const float* __restrict__ bias)
{
    __shared__ __align__(16) float sW[PD][68];
    __shared__ __align__(16) float sIn[64][68];

    const int tid = threadIdx.x;
    const int r0  = blockIdx.x * 64;               // global row among 2*BH*LQ
    const bool isQ = (r0 < PBH * PLQ);
    const int rr0  = isQ ? r0 : (r0 - PBH * PLQ);
    const float* in = (isQ ? Q : K) + (size_t)rr0 * PD;
    const int woff = isQ ? 0 : PD;

    // Stage 64 input rows (coalesced float4)
    for (int i = tid; i < 64 * (PD / 4); i += 256) {
        int r = i >> 4, d4 = i & 15;
        float4 v = ((const float4*)(in + (size_t)r * PD))[d4];
        *(float4*)&sIn[r][d4 * 4] = v;
    }
    // Stage W half (e-major rows)
    for (int i = tid; i < PD * (PD / 4); i += 256) {
        int e = i >> 4, d4 = i & 15;
        float4 v = *(const float4*)(W + (size_t)e * (2 * PD) + woff + d4 * 4);
        *(float4*)&sW[e][d4 * 4] = v;
    }
    __syncthreads();

    const int e  = tid & 63;
    const int rg = tid >> 6;       // 4 groups x 16 rows
    const float b = isQ ? bias[e] : 0.0f;

    float acc[16];
#pragma unroll
    for (int r = 0; r < 16; r++) acc[r] = b;

#pragma unroll
    for (int d4 = 0; d4 < PD / 4; d4++) {
        float4 wv = *(const float4*)&sW[e][d4 * 4];
#pragma unroll
        for (int r = 0; r < 16; r++) {
            float4 iv = *(const float4*)&sIn[rg * 16 + r][d4 * 4]; // broadcast
            acc[r] += wv.x * iv.x + wv.y * iv.y + wv.z * iv.z + wv.w * iv.w;
        }
    }

    float* dst = (isQ ? g_qp : g_kp) + (size_t)rr0 * PD;
#pragma unroll
    for (int r = 0; r < 16; r++)
        dst[(size_t)(rg * 16 + r) * PD + e] = acc[r];   // coalesced STG.32
}

// ---------------------------------------------------------------------------
// Main kernel: one block = (bh, 4 consecutive q rows), all 512 k.
//   NO register cap (R7/R9 lesson: caps below natural demand -> spills ->
//   DRAM 24-30%, issue <10%). Instead shrink natural demand:
//   TQ=4 (acc[4]) + kp quarters (ka[4]) ~= 80-110 regs, 128-thread blocks
//   -> 4-5 CTAs/SM = 4-5 warps/SMSP (R5 had 2/SMSP at issue 21%).
//   Phase 1: logits[q][k] = sum_e w[e]*tanh(qp[q,e] + kp[k,e])
//   Phase 2: per-warp masked softmax (4 warps = 4 q rows), write weights.
// Grid: BH * (LQ/TQ) = 1024 blocks, 128 threads.
// ---------------------------------------------------------------------------
__global__ __launch_bounds__(128) void attn_kernel(
    const int* __restrict__ mask,
    const float* __restrict__ w_logit,
    float* __restrict__ out)
{
    __shared__ __align__(16) float qp_s[TQ][PD];   // 1 KB
    __shared__ __align__(16) float ws[PD];         // 256 B
    __shared__ float logits_s[TQ][PLKV];           // 8 KB

    const int bh  = blockIdx.x / (PLQ / TQ);
    const int qt  = blockIdx.x % (PLQ / TQ);
    const int q0  = qt * TQ;
    const int tid = threadIdx.x;

    // Load qp tile (TQ*D = 256 floats) and w_logit into shared
    const float* qpbase = g_qp + ((size_t)bh * PLQ + q0) * PD;
    for (int i = tid; i < TQ * PD; i += 128)
        ((float*)qp_s)[i] = qpbase[i];
    if (tid < PD) ws[tid] = w_logit[tid];
    __syncthreads();

    const float*  kpbase = g_kp + (size_t)bh * PLKV * PD;
    const float4* ws4    = (const float4*)ws;

    // ---- Phase 1: logits ----
    for (int c = 0; c < PLKV; c += 128) {
        const int k = c + tid;
        const float4* kp4 = (const float4*)(kpbase + (size_t)k * PD);

        float acc[TQ];
#pragma unroll
        for (int q = 0; q < TQ; q++) acc[q] = 0.0f;

#pragma unroll
        for (int quarter = 0; quarter < 4; quarter++) {
            float4 ka[4];                       // 16 e-values of kp
#pragma unroll
            for (int i = 0; i < 4; i++) ka[i] = kp4[quarter * 4 + i]; // batched LDG

#pragma unroll
            for (int q = 0; q < TQ; q++) {
                const float4* qp4 = (const float4*)qp_s[q];
                float a0 = 0.0f, a1 = 0.0f;
#pragma unroll
                for (int e4 = 0; e4 < 4; e4++) {
                    float4 qv = qp4[quarter * 4 + e4];   // broadcast LDS.128
                    float4 wv = ws4[quarter * 4 + e4];   // broadcast LDS.128
                    a0 += wv.x * tanh_fast(qv.x + ka[e4].x);
                    a1 += wv.y * tanh_fast(qv.y + ka[e4].y);
                    a0 += wv.z * tanh_fast(qv.z + ka[e4].z);
                    a1 += wv.w * tanh_fast(qv.w + ka[e4].w);
                }
                acc[q] += a0 + a1;
            }
        }
#pragma unroll
        for (int q = 0; q < TQ; q++)
            logits_s[q][k] = acc[q];
    }
    __syncthreads();

    // ---- Phase 2: masked softmax, one warp per q row (4 warps) ----
    const int w    = tid >> 5;
    const int lane = tid & 31;
    const int qg   = q0 + w;
    const int b    = bh / PH;
    const int* mrow = mask + ((size_t)b * PLQ + qg) * PLKV;

    float m_val = -FLT_MAX, m_raw = -FLT_MAX;
    int anyv = 0;
    for (int j = lane; j < PLKV; j += 32) {
        float l = logits_s[w][j];
        int   v = mrow[j] != 0;
        anyv |= v;
        m_raw = fmaxf(m_raw, l);
        if (v) m_val = fmaxf(m_val, l);
    }
#pragma unroll
    for (int o = 16; o; o >>= 1) {
        m_val = fmaxf(m_val, __shfl_xor_sync(0xffffffffu, m_val, o));
        m_raw = fmaxf(m_raw, __shfl_xor_sync(0xffffffffu, m_raw, o));
    }
    const bool any = __ballot_sync(0xffffffffu, anyv) != 0;
    const float M = any ? m_val : m_raw;

    float s = 0.0f;
    for (int j = lane; j < PLKV; j += 32) {
        float l = logits_s[w][j];
        bool  v = (!any) || (mrow[j] != 0);
        float p = v ? __expf(l - M) : 0.0f;
        logits_s[w][j] = p;
        s += p;
    }
#pragma unroll
    for (int o = 16; o; o >>= 1)
        s += __shfl_xor_sync(0xffffffffu, s, o);
    const float inv = 1.0f / s;

    float* orow = out + ((size_t)bh * PLQ + qg) * PLKV;
    for (int j = lane; j < PLKV; j += 32)
        orow[j] = logits_s[w][j] * inv;
}

// ---------------------------------------------------------------------------
// Inputs (metadata order): queries, keys, values(unused), mask(int32),
// W_concat, b_concat, w_logit, b_logit(unused: softmax shift-invariant)
// ---------------------------------------------------------------------------
extern "C" void kernel_launch(void* const* d_in, const int* in_sizes, int n_in,
                              void* d_out, int out_size)
{
    const float* Q    = (const float*)d_in[0];
    const float* K    = (const float*)d_in[1];
    const int*   mask = (const int*)d_in[3];
    const float* W    = (const float*)d_in[4];
    const float* bc   = (const float*)d_in[5];
    const float* wl   = (const float*)d_in[6];
    float*       out  = (float*)d_out;

    proj_kernel<<<(2 * PBH * PLQ) / 64, 256>>>(Q, K, W, bc);
    attn_kernel<<<PBH * (PLQ / TQ), 128>>>(mask, wl, out);
}